// round 5
// baseline (speedup 1.0000x reference)
#include <cuda_runtime.h>
#include <math.h>

// Problem shapes (fixed by the dataset's setup_inputs)
#define BATCH   2
#define NMAPS   16
#define CH      256
#define HWPIX   4096   // 64*64
#define TDIM    1024
#define PIX     32     // pixels per block tile
#define NPQ     (PIX/4)             // 8 pixel-quads
#define NTHREADS 256
#define SMEM_BYTES (2 * CH * PIX * 4)   // two 32KB x-slab buffers

// Intermediates in device globals (no allocation allowed)
__device__ float  g_q[BATCH * CH];     // q = tr @ Wq^T + bq
__device__ float  g_qk[BATCH * CH];    // qk = scale * Wk^T q
__device__ float4 g_wvp[128 * 128];    // paired Wv: [P][c/2] = {w(2P,c),w(2P+1,c),w(2P,c+1),w(2P+1,c+1)}

// ---------------- f32x2 packed-FP32 helpers (Blackwell dual-FP32 pipe) ----------------
__device__ __forceinline__ unsigned long long pk2(float lo, float hi) {
    unsigned long long r;
    asm("mov.b64 %0, {%1, %2};" : "=l"(r) : "f"(lo), "f"(hi));
    return r;
}
__device__ __forceinline__ unsigned long long splat2(float v) {
    unsigned long long r;
    asm("mov.b64 %0, {%1, %1};" : "=l"(r) : "f"(v));
    return r;
}
__device__ __forceinline__ void fma2(unsigned long long& d, unsigned long long a, unsigned long long b) {
    asm("fma.rn.f32x2 %0, %1, %2, %0;" : "+l"(d) : "l"(a), "l"(b));
}
__device__ __forceinline__ void upk2(float& lo, float& hi, unsigned long long v) {
    asm("mov.b64 {%0, %1}, %2;" : "=f"(lo), "=f"(hi) : "l"(v));
}

// ---------------- cp.async helpers ----------------
__device__ __forceinline__ void cp16(float* dst_smem, const float* src) {
    unsigned d = (unsigned)__cvta_generic_to_shared(dst_smem);
    asm volatile("cp.async.cg.shared.global [%0], [%1], 16;" :: "r"(d), "l"(src));
}
__device__ __forceinline__ void cp_commit() { asm volatile("cp.async.commit_group;" ::: "memory"); }
__device__ __forceinline__ void cp_wait0()  { asm volatile("cp.async.wait_group 0;" ::: "memory"); }
__device__ __forceinline__ void cp_wait1()  { asm volatile("cp.async.wait_group 1;" ::: "memory"); }

// ---------------- Prep 1: q[b][o] = tr[b,:]·Wq[o,:] + bq[o] ----------------
// grid (32, B) x 256; warp per output channel o; float4 loads, deep MLP.
__global__ void __launch_bounds__(256) prep1_kernel(
    const float* __restrict__ tr, const float* __restrict__ Wq,
    const float* __restrict__ bq)
{
    const int b    = blockIdx.y;
    const int lane = threadIdx.x & 31;
    const int wid  = threadIdx.x >> 5;
    const int o    = blockIdx.x * 8 + wid;

    const float4* w4 = (const float4*)(Wq + (size_t)o * TDIM);
    const float4* t4 = (const float4*)(tr + (size_t)b * TDIM);
    float a0 = 0.f, a1 = 0.f, a2 = 0.f, a3 = 0.f;
    #pragma unroll
    for (int k = 0; k < 8; k++) {
        float4 w = w4[lane + 32 * k];
        float4 t = t4[lane + 32 * k];
        a0 += w.x * t.x; a1 += w.y * t.y; a2 += w.z * t.z; a3 += w.w * t.w;
    }
    float acc = (a0 + a1) + (a2 + a3);
    #pragma unroll
    for (int off = 16; off > 0; off >>= 1) acc += __shfl_xor_sync(0xffffffffu, acc, off);
    if (lane == 0) g_q[b * CH + o] = acc + bq[o];
}

// ---------------- Prep 2: qk[b][c] = scale * sum_o q[b,o]*Wk[o,c] ----------------
__global__ void __launch_bounds__(256) prep2_kernel(const float* __restrict__ Wk)
{
    __shared__ float part[8][32];
    const int b  = blockIdx.y;
    const int c0 = blockIdx.x * 32;
    const int og = threadIdx.x >> 5;
    const int ci = threadIdx.x & 31;
    const int c  = c0 + ci;

    const float* qb = g_q + b * CH;
    float acc = 0.f;
    #pragma unroll 8
    for (int i = 0; i < 32; i++) {
        int o = og * 32 + i;
        acc += qb[o] * Wk[(size_t)o * CH + c];
    }
    part[og][ci] = acc;
    __syncthreads();
    if (threadIdx.x < 32) {
        float s = part[0][ci] + part[1][ci] + part[2][ci] + part[3][ci]
                + part[4][ci] + part[5][ci] + part[6][ci] + part[7][ci];
        g_qk[b * CH + c0 + ci] = s * 0.0625f;   // CH^-0.5
    }
}

// ---------------- Prep 3: pair Wv rows for f32x2 epilogue ----------------
// g_wvp[P*128 + c2] = { Wv[2P][2c2], Wv[2P+1][2c2], Wv[2P][2c2+1], Wv[2P+1][2c2+1] }
__global__ void __launch_bounds__(256) prep3_kernel(const float* __restrict__ Wv)
{
    const int idx = blockIdx.x * 256 + threadIdx.x;   // 0..16383
    const int P   = idx >> 7;
    const int c2  = idx & 127;
    const float2 r0 = *(const float2*)(Wv + (size_t)(2 * P)     * CH + 2 * c2);
    const float2 r1 = *(const float2*)(Wv + (size_t)(2 * P + 1) * CH + 2 * c2);
    g_wvp[idx] = make_float4(r0.x, r1.x, r0.y, r1.y);
}

// ---------------- Main: fused scores + online softmax + weighted sum + f32x2 GEMM ----------------
__global__ void __launch_bounds__(NTHREADS, 2) main_kernel(
    const float* __restrict__ xg, const float* __restrict__ bv,
    float* __restrict__ out)
{
    extern __shared__ float smem[];          // 2 buffers of CH*PIX floats
    __shared__ float qk_s[CH];
    __shared__ float red_s[PIX][33];         // [pixel][cg], padded pitch
    __shared__ __align__(16) float w_s[PIX];
    __shared__ __align__(16) float corr_s[PIX];
    __shared__ float rmax_s[PIX];
    __shared__ float rsum_s[PIX];

    const int tid  = threadIdx.x;
    const int b    = blockIdx.x / (HWPIX / PIX);
    const int pix0 = (blockIdx.x % (HWPIX / PIX)) * PIX;

    float* buf[2] = { smem, smem + CH * PIX };

    for (int i = tid; i < CH; i += NTHREADS) qk_s[i] = g_qk[b * CH + i];
    if (tid < PIX) { rmax_s[tid] = -1e30f; rsum_s[tid] = 0.f; }

    // Thread owns channels cg*8..cg*8+7 and pixel quad pq (pixels 4pq..4pq+3)
    const int cg = tid >> 3;   // 0..31
    const int pq = tid & 7;    // 0..7

    const float* base = xg + (size_t)b * NMAPS * CH * HWPIX + pix0;

    // prologue: stage slab 0 -> buf0
    {
        const float* bm = base;
        #pragma unroll
        for (int k = 0; k < 8; k++) {
            int i4 = tid + k * NTHREADS;     // 0..2047
            int c  = i4 >> 3;
            int q  = i4 & 7;
            cp16(buf[0] + i4 * 4, bm + (size_t)c * HWPIX + 4 * q);
        }
        cp_commit();
    }
    __syncthreads();   // qk_s / softmax state visible

    float qkr[8];
    #pragma unroll
    for (int i = 0; i < 8; i++) qkr[i] = qk_s[cg * 8 + i];

    float4 yacc[8];
    #pragma unroll
    for (int i = 0; i < 8; i++) yacc[i] = make_float4(0.f, 0.f, 0.f, 0.f);

    for (int m = 0; m < NMAPS; m++) {
        float* bufc = buf[m & 1];
        if (m + 1 < NMAPS) {
            float* bufn = buf[(m + 1) & 1];
            const float* bm = base + (size_t)(m + 1) * CH * HWPIX;
            #pragma unroll
            for (int k = 0; k < 8; k++) {
                int i4 = tid + k * NTHREADS;
                int c  = i4 >> 3;
                int q  = i4 & 7;
                cp16(bufn + i4 * 4, bm + (size_t)c * HWPIX + 4 * q);
            }
            cp_commit();
            cp_wait1();
        } else {
            cp_wait0();
        }
        __syncthreads();   // sync A: current buffer ready; red_s free

        // Phase A: x -> registers; partial scores for this thread's 4 pixels
        float4 xv[8];
        float4 ps = make_float4(0.f, 0.f, 0.f, 0.f);
        {
            const float4* x4 = (const float4*)bufc;
            #pragma unroll
            for (int i = 0; i < 8; i++) {
                int c = cg * 8 + i;
                xv[i] = x4[c * NPQ + pq];
                ps.x += qkr[i] * xv[i].x;
                ps.y += qkr[i] * xv[i].y;
                ps.z += qkr[i] * xv[i].z;
                ps.w += qkr[i] * xv[i].w;
            }
            red_s[4 * pq + 0][cg] = ps.x;
            red_s[4 * pq + 1][cg] = ps.y;
            red_s[4 * pq + 2][cg] = ps.z;
            red_s[4 * pq + 3][cg] = ps.w;
        }
        __syncthreads();   // sync B: bufc reads + red_s writes done

        // Reduce 32 cg-partials per pixel + online softmax (32 threads)
        if (tid < PIX) {
            float s0 = 0.f, s1 = 0.f, s2 = 0.f, s3 = 0.f;
            #pragma unroll
            for (int g = 0; g < 32; g += 4) {
                s0 += red_s[tid][g];
                s1 += red_s[tid][g + 1];
                s2 += red_s[tid][g + 2];
                s3 += red_s[tid][g + 3];
            }
            float s  = (s0 + s1) + (s2 + s3);
            float om = rmax_s[tid];
            float nm = fmaxf(om, s);
            float cr = __expf(om - nm);
            float w  = __expf(s - nm);
            rsum_s[tid] = rsum_s[tid] * cr + w;
            rmax_s[tid] = nm;
            w_s[tid]    = w;
            corr_s[tid] = cr;
        }
        __syncthreads();   // sync C: w/corr ready

        // Phase B: y = y*corr + w*x  (pure register work)
        {
            float4 wv = *(const float4*)&w_s[4 * pq];
            float4 cv = *(const float4*)&corr_s[4 * pq];
            #pragma unroll
            for (int i = 0; i < 8; i++) {
                yacc[i].x = yacc[i].x * cv.x + wv.x * xv[i].x;
                yacc[i].y = yacc[i].y * cv.y + wv.y * xv[i].y;
                yacc[i].z = yacc[i].z * cv.z + wv.z * xv[i].z;
                yacc[i].w = yacc[i].w * cv.w + wv.w * xv[i].w;
            }
        }
        // no sync: next prefetch targets bufc, whose reads all precede sync B
    }

    // normalize y into buf0 (free: last slab lives in buf1)
    __syncthreads();
    {
        float4 rs = *(const float4*)&rsum_s[4 * pq];
        float4 inv = make_float4(1.f / rs.x, 1.f / rs.y, 1.f / rs.z, 1.f / rs.w);
        float4* y4 = (float4*)buf[0];
        #pragma unroll
        for (int i = 0; i < 8; i++) {
            int c = cg * 8 + i;
            y4[c * NPQ + pq] = make_float4(yacc[i].x * inv.x, yacc[i].y * inv.y,
                                           yacc[i].z * inv.z, yacc[i].w * inv.w);
        }
    }
    __syncthreads();

    // Epilogue GEMM via packed f32x2: out[o,p] = sum_c Wv[o,c]*y[c,p] + bv[o]
    // Thread owns o-pairs P = og*4+k (o = og*8..og*8+7) x 4 pixels (4pq..+3)
    {
        const int og = tid >> 3;   // 0..31 (same as cg)
        unsigned long long acc2[4][4];   // [pair k][pixel j] packed (o_even, o_odd)
        #pragma unroll
        for (int k = 0; k < 4; k++) {
            unsigned long long bp = pk2(bv[og * 8 + 2 * k], bv[og * 8 + 2 * k + 1]);
            #pragma unroll
            for (int j = 0; j < 4; j++) acc2[k][j] = bp;
        }
        const float4* y4 = (const float4*)buf[0];

        #pragma unroll 2
        for (int c2 = 0; c2 < 128; c2++) {       // c = 2*c2, 2*c2+1
            float4 y0 = y4[(2 * c2 + 0) * NPQ + pq];
            float4 y1 = y4[(2 * c2 + 1) * NPQ + pq];
            unsigned long long ys0[4], ys1[4];
            ys0[0] = splat2(y0.x); ys0[1] = splat2(y0.y); ys0[2] = splat2(y0.z); ys0[3] = splat2(y0.w);
            ys1[0] = splat2(y1.x); ys1[1] = splat2(y1.y); ys1[2] = splat2(y1.z); ys1[3] = splat2(y1.w);
            #pragma unroll
            for (int k = 0; k < 4; k++) {
                float4 wp = g_wvp[(size_t)(og * 4 + k) * 128 + c2];
                unsigned long long wc0 = pk2(wp.x, wp.y);
                unsigned long long wc1 = pk2(wp.z, wp.w);
                #pragma unroll
                for (int j = 0; j < 4; j++) {
                    fma2(acc2[k][j], wc0, ys0[j]);
                    fma2(acc2[k][j], wc1, ys1[j]);
                }
            }
        }

        // unpack + vectorized stores: one float4 (4 pixels) per output channel
        #pragma unroll
        for (int k = 0; k < 4; k++) {
            float lo[4], hi[4];
            #pragma unroll
            for (int j = 0; j < 4; j++) upk2(lo[j], hi[j], acc2[k][j]);
            int o0 = og * 8 + 2 * k;
            float* dst0 = out + ((size_t)b * CH + o0)     * HWPIX + pix0 + 4 * pq;
            float* dst1 = out + ((size_t)b * CH + o0 + 1) * HWPIX + pix0 + 4 * pq;
            *(float4*)dst0 = make_float4(lo[0], lo[1], lo[2], lo[3]);
            *(float4*)dst1 = make_float4(hi[0], hi[1], hi[2], hi[3]);
        }
    }
}

extern "C" void kernel_launch(void* const* d_in, const int* in_sizes, int n_in,
                              void* d_out, int out_size)
{
    const float* tr = (const float*)d_in[0];   // [B, T]
    const float* x  = (const float*)d_in[1];   // [B, M, C, H, W]
    const float* Wq = (const float*)d_in[2];   // [C, T]
    const float* bq = (const float*)d_in[3];   // [C]
    const float* Wk = (const float*)d_in[4];   // [C, C]
    // d_in[5] = bk: constant across the softmax axis -> cancels, unused
    const float* Wv = (const float*)d_in[6];   // [C, C]
    const float* bv = (const float*)d_in[7];   // [C]
    float* out = (float*)d_out;                // [B, C, H, W]

    (void)in_sizes; (void)n_in; (void)out_size;

    cudaFuncSetAttribute(main_kernel, cudaFuncAttributeMaxDynamicSharedMemorySize, SMEM_BYTES);

    prep1_kernel<<<dim3(32, BATCH), 256>>>(tr, Wq, bq);
    prep2_kernel<<<dim3(8, BATCH), 256>>>(Wk);
    prep3_kernel<<<64, 256>>>(Wv);
    main_kernel<<<BATCH * (HWPIX / PIX), NTHREADS, SMEM_BYTES>>>(x, bv, out);
}